// round 8
// baseline (speedup 1.0000x reference)
#include <cuda_runtime.h>

#define HW    4096
#define CDIM  256
#define BATCH 32
#define NH    4
#define HID   64
#define NSEL  40
#define KCX   8      // k per chunk
#define BMX   256    // pixels per block tile

// Scratch (device globals: allocation-free rule)
__device__ float g_imp[BATCH * HW];
__device__ int   g_selidx[BATCH * NSEL];
__device__ float g_w1t[CDIM * HID];   // W1 transposed: [c][o]

__device__ __forceinline__ unsigned long long splat2(float v) {
    unsigned long long r;
    asm("mov.b64 %0, {%1, %1};" : "=l"(r) : "r"(__float_as_uint(v)));
    return r;
}
__device__ __forceinline__ void ffma2(unsigned long long& d, unsigned long long a,
                                      unsigned long long b) {
    asm("fma.rn.f32x2 %0, %1, %2, %0;" : "+l"(d) : "l"(a), "l"(b));
}

// ---------------------------------------------------------------------------
// K0: transpose W1 [o][c] -> [c][o] so tile loads are coalesced.
// ---------------------------------------------------------------------------
__global__ void transpose_w1(const float* __restrict__ w1) {
    int i = blockIdx.x * 256 + threadIdx.x;   // 16384 elems
    int o = i >> 8, c = i & 255;
    g_w1t[c * HID + o] = w1[i];
}

// ---------------------------------------------------------------------------
// K1: fused modulator + output write.
//   GEMM tile 256px x 64hid x 256k, 256 thr, 8px x 8hid micro-tile (f32x2).
//   A-loads are 8-way warp-broadcast; 4 LDS.128 per 32 FFMA2 (crossbar-safe).
//   Layer2 reduced via shfl (8-lane groups), sigmoid in regs.
//   Epilogue: out = x * scale for own tile (x re-read is L2-hot).
// ---------------------------------------------------------------------------
__global__ __launch_bounds__(256, 2) void mod_fused_kernel(
    const float* __restrict__ x,  const float* __restrict__ b1,
    const float* __restrict__ w2, const float* __restrict__ b2,
    float* __restrict__ out)
{
    __shared__ float sA[2][KCX * BMX];   // 2 x 8KB
    __shared__ float sB[2][KCX * HID];   // 2 x 2KB
    __shared__ float sImp[4 * BMX];
    __shared__ float sScale[BMX];
    __shared__ float sW2[NH * HID];
    __shared__ float sB1[HID];
    __shared__ float sB2[NH];

    const int tid = threadIdx.x;
    const int b   = blockIdx.x >> 4;            // 16 tiles of 256px per batch
    const int p0  = (blockIdx.x & 15) << 8;
    const float* xb = x + (size_t)b * CDIM * HW + p0;

    sW2[tid & 255] = w2[tid & 255];
    if (tid < HID) sB1[tid] = b1[tid];
    if (tid < NH)  sB2[tid] = b2[tid];

    // loader mapping
    const int la_c  = tid >> 6;                 // 0..3 (c rows; +4 for second)
    const int la_p4 = (tid & 63) << 2;          // px group of 4
    const int lb_c  = tid >> 5;                 // 0..7
    const int lb_o2 = (tid & 31) << 1;          // hid pair
    // compute mapping
    const int tx = tid & 7;                     // hid: o = tx*8 .. +7
    const int ty = tid >> 3;                    // px:  p = ty*8 .. +7

    unsigned long long acc[4][8];
#pragma unroll
    for (int j = 0; j < 4; ++j)
#pragma unroll
        for (int o = 0; o < 8; ++o) acc[j][o] = 0ull;
    float imp4[4] = {0.f, 0.f, 0.f, 0.f};

    float4 ra0, ra1; float2 rb;

    // prologue: chunk 0
    ra0 = *(const float4*)(xb + (size_t)la_c * HW + la_p4);
    ra1 = *(const float4*)(xb + (size_t)(la_c + 4) * HW + la_p4);
    rb  = *(const float2*)(g_w1t + lb_c * HID + lb_o2);
    *(float4*)(&sA[0][la_c * BMX + la_p4])       = ra0;
    *(float4*)(&sA[0][(la_c + 4) * BMX + la_p4]) = ra1;
    *(float2*)(&sB[0][lb_c * HID + lb_o2])       = rb;
    imp4[0] += fabsf(ra0.x) + fabsf(ra1.x);
    imp4[1] += fabsf(ra0.y) + fabsf(ra1.y);
    imp4[2] += fabsf(ra0.z) + fabsf(ra1.z);
    imp4[3] += fabsf(ra0.w) + fabsf(ra1.w);
    __syncthreads();

    int buf = 0;
#pragma unroll 1
    for (int ch = 0; ch < CDIM / KCX; ++ch) {
        if (ch < CDIM / KCX - 1) {              // prefetch next chunk
            int c0 = (ch + 1) * KCX;
            ra0 = *(const float4*)(xb + (size_t)(c0 + la_c) * HW + la_p4);
            ra1 = *(const float4*)(xb + (size_t)(c0 + la_c + 4) * HW + la_p4);
            rb  = *(const float2*)(g_w1t + (c0 + lb_c) * HID + lb_o2);
        }
#pragma unroll
        for (int k = 0; k < KCX; ++k) {
            const float* A  = &sA[buf][k * BMX + (ty << 3)];
            const float* Bp = &sB[buf][k * HID + (tx << 3)];
            ulonglong2 a01 = *(const ulonglong2*)A;
            ulonglong2 a23 = *(const ulonglong2*)(A + 4);
            float4 bv0 = *(const float4*)Bp;
            float4 bv1 = *(const float4*)(Bp + 4);
            unsigned long long s0 = splat2(bv0.x), s1 = splat2(bv0.y);
            unsigned long long s2 = splat2(bv0.z), s3 = splat2(bv0.w);
            unsigned long long s4 = splat2(bv1.x), s5 = splat2(bv1.y);
            unsigned long long s6 = splat2(bv1.z), s7 = splat2(bv1.w);
            ffma2(acc[0][0], a01.x, s0); ffma2(acc[0][1], a01.x, s1);
            ffma2(acc[0][2], a01.x, s2); ffma2(acc[0][3], a01.x, s3);
            ffma2(acc[0][4], a01.x, s4); ffma2(acc[0][5], a01.x, s5);
            ffma2(acc[0][6], a01.x, s6); ffma2(acc[0][7], a01.x, s7);
            ffma2(acc[1][0], a01.y, s0); ffma2(acc[1][1], a01.y, s1);
            ffma2(acc[1][2], a01.y, s2); ffma2(acc[1][3], a01.y, s3);
            ffma2(acc[1][4], a01.y, s4); ffma2(acc[1][5], a01.y, s5);
            ffma2(acc[1][6], a01.y, s6); ffma2(acc[1][7], a01.y, s7);
            ffma2(acc[2][0], a23.x, s0); ffma2(acc[2][1], a23.x, s1);
            ffma2(acc[2][2], a23.x, s2); ffma2(acc[2][3], a23.x, s3);
            ffma2(acc[2][4], a23.x, s4); ffma2(acc[2][5], a23.x, s5);
            ffma2(acc[2][6], a23.x, s6); ffma2(acc[2][7], a23.x, s7);
            ffma2(acc[3][0], a23.y, s0); ffma2(acc[3][1], a23.y, s1);
            ffma2(acc[3][2], a23.y, s2); ffma2(acc[3][3], a23.y, s3);
            ffma2(acc[3][4], a23.y, s4); ffma2(acc[3][5], a23.y, s5);
            ffma2(acc[3][6], a23.y, s6); ffma2(acc[3][7], a23.y, s7);
        }
        if (ch < CDIM / KCX - 1) {
            __syncthreads();
            buf ^= 1;
            *(float4*)(&sA[buf][la_c * BMX + la_p4])       = ra0;
            *(float4*)(&sA[buf][(la_c + 4) * BMX + la_p4]) = ra1;
            *(float2*)(&sB[buf][lb_c * HID + lb_o2])       = rb;
            imp4[0] += fabsf(ra0.x) + fabsf(ra1.x);
            imp4[1] += fabsf(ra0.y) + fabsf(ra1.y);
            imp4[2] += fabsf(ra0.z) + fabsf(ra1.z);
            imp4[3] += fabsf(ra0.w) + fabsf(ra1.w);
            __syncthreads();
        }
    }

    // importance partials
    *(float4*)(&sImp[la_c * BMX + la_p4]) = make_float4(imp4[0], imp4[1], imp4[2], imp4[3]);

    // layer2: z[px][h] partials over this thread's 8-hid slice, then shfl-reduce
    float z[8][NH];
#pragma unroll
    for (int p = 0; p < 8; ++p)
#pragma unroll
        for (int h = 0; h < NH; ++h) z[p][h] = 0.f;

#pragma unroll
    for (int j = 0; j < 4; ++j) {
#pragma unroll
        for (int o = 0; o < 8; ++o) {
            unsigned int lo, hi;
            asm("mov.b64 {%0, %1}, %2;" : "=r"(lo), "=r"(hi) : "l"(acc[j][o]));
            float bo = sB1[(tx << 3) + o];
            float h1lo = fmaxf(__uint_as_float(lo) + bo, 0.f);
            float h1hi = fmaxf(__uint_as_float(hi) + bo, 0.f);
#pragma unroll
            for (int h = 0; h < NH; ++h) {
                float w = sW2[h * HID + (tx << 3) + o];
                z[2 * j][h]     = fmaf(w, h1lo, z[2 * j][h]);
                z[2 * j + 1][h] = fmaf(w, h1hi, z[2 * j + 1][h]);
            }
        }
    }
    // reduce across tx (8-lane groups stay intact under xor 1,2,4)
#pragma unroll
    for (int s = 1; s < 8; s <<= 1)
#pragma unroll
        for (int p = 0; p < 8; ++p)
#pragma unroll
            for (int h = 0; h < NH; ++h)
                z[p][h] += __shfl_xor_sync(0xffffffffu, z[p][h], s);

    if (tx == 0) {
#pragma unroll
        for (int p = 0; p < 8; ++p) {
            float msum = 0.f;
#pragma unroll
            for (int h = 0; h < NH; ++h)
                msum += 1.f / (1.f + expf(-(z[p][h] + sB2[h])));
            sScale[(ty << 3) + p] = 0.7f * 0.25f * msum;
        }
    }
    __syncthreads();

    // finalize importance
    g_imp[b * HW + p0 + tid] =
        sImp[tid] + sImp[BMX + tid] + sImp[2 * BMX + tid] + sImp[3 * BMX + tid];

    // epilogue: out = x * scale over own tile (x L2-hot)
    {
        const int ep = (tid & 63) << 2;
        float4 scl = *(const float4*)(&sScale[ep]);
        const float* xr = xb + ep;
        float* orow = out + (size_t)b * CDIM * HW + p0 + ep;
#pragma unroll 4
        for (int c = tid >> 6; c < CDIM; c += 4) {
            float4 xv = __ldg((const float4*)(xr + (size_t)c * HW));
            float4 ov;
            ov.x = xv.x * scl.x; ov.y = xv.y * scl.y;
            ov.z = xv.z * scl.z; ov.w = xv.w * scl.w;
            *(float4*)(orow + (size_t)c * HW) = ov;
        }
    }
}

// ---------------------------------------------------------------------------
// K2: per-batch top-40 tournament; record selected indices.
//     (softmax rows sum to 1 => graph pixel importance == 1/NSEL exactly)
// ---------------------------------------------------------------------------
__global__ __launch_bounds__(1024) void topk_kernel()
{
    __shared__ unsigned long long sW[32];
    __shared__ unsigned long long sBest;
    const int b = blockIdx.x, tid = threadIdx.x;
    const int base = tid << 2;

    float4 v4 = *(const float4*)(g_imp + b * HW + base);
    float v[4] = {v4.x, v4.y, v4.z, v4.w};   // strictly positive sums of |x|

    for (int it = 0; it < NSEL; ++it) {
        unsigned long long k = 0ull;
#pragma unroll
        for (int j = 0; j < 4; ++j) {
            unsigned long long kj =
                ((unsigned long long)__float_as_uint(v[j]) << 32) |
                (unsigned)(HW - 1 - (base + j));   // tie -> lower idx wins
            k = (kj > k) ? kj : k;
        }
#pragma unroll
        for (int s = 16; s; s >>= 1) {
            unsigned long long o = __shfl_xor_sync(0xffffffffu, k, s);
            k = (o > k) ? o : k;
        }
        if ((tid & 31) == 0) sW[tid >> 5] = k;
        __syncthreads();
        if (tid < 32) {
            unsigned long long kk = sW[tid];
#pragma unroll
            for (int s = 16; s; s >>= 1) {
                unsigned long long o = __shfl_xor_sync(0xffffffffu, kk, s);
                kk = (o > kk) ? o : kk;
            }
            if (tid == 0) sBest = kk;
        }
        __syncthreads();
        int idx = (HW - 1) - (int)(unsigned)(sBest & 0xffffffffu);
        if ((idx >> 2) == tid) {
            v[idx & 3] = 0.0f;
            g_selidx[b * NSEL + it] = idx;
        }
    }
}

// ---------------------------------------------------------------------------
// K4: out[b,c,p] += (0.3/NSEL) * x[b,c,p] for the NSEL selected pixels.
// ---------------------------------------------------------------------------
__global__ __launch_bounds__(256) void add_sel_kernel(const float* __restrict__ x,
                                                      float* __restrict__ out)
{
    const int b = blockIdx.x;
    const int c = threadIdx.x;
#pragma unroll 1
    for (int it = 0; it < NSEL; ++it) {
        int p = g_selidx[b * NSEL + it];
        size_t idx = (((size_t)(b * CDIM + c)) << 12) + p;
        out[idx] += (0.3f / (float)NSEL) * x[idx];
    }
}

// ---------------------------------------------------------------------------
extern "C" void kernel_launch(void* const* d_in, const int* in_sizes, int n_in,
                              void* d_out, int out_size)
{
    const float* x  = (const float*)d_in[0];
    const float* w1 = (const float*)d_in[1];
    const float* b1 = (const float*)d_in[2];
    const float* w2 = (const float*)d_in[3];
    const float* b2 = (const float*)d_in[4];
    float* out = (float*)d_out;

    transpose_w1<<<64, 256>>>(w1);
    mod_fused_kernel<<<BATCH * (HW / BMX), 256>>>(x, b1, w2, b2, out);
    topk_kernel<<<BATCH, 1024>>>();
    add_sel_kernel<<<BATCH, 256>>>(x, out);
}

// round 11
// speedup vs baseline: 1.3454x; 1.3454x over previous
#include <cuda_runtime.h>

#define HW    4096
#define CDIM  256
#define BATCH 32
#define NH    4
#define HID   64
#define NSEL  40
#define KC    16
#define BM    128

// Scratch (device globals: allocation-free rule)
__device__ float g_scale[BATCH * HW];
__device__ float g_imp[BATCH * HW];
__device__ float g_w1t[CDIM * HID];   // W1 transposed: [c][o]

__device__ __forceinline__ unsigned long long splat2(float v) {
    unsigned long long r;
    asm("mov.b64 %0, {%1, %1};" : "=l"(r) : "r"(__float_as_uint(v)));
    return r;
}
__device__ __forceinline__ void ffma2(unsigned long long& d, unsigned long long a,
                                      unsigned long long b) {
    asm("fma.rn.f32x2 %0, %1, %2, %0;" : "+l"(d) : "l"(a), "l"(b));
}

// ---------------------------------------------------------------------------
// K0: transpose W1 [o][c] -> [c][o] so tile loads are coalesced.
// ---------------------------------------------------------------------------
__global__ void transpose_w1(const float* __restrict__ w1) {
    int i = blockIdx.x * 256 + threadIdx.x;   // 16384 elems
    int o = i >> 8, c = i & 255;
    g_w1t[c * HID + o] = w1[i];
}

// ---------------------------------------------------------------------------
// K1: register-tiled GEMM [128px x 64hid x 256k] per block + fused importance.
//     4x4 micro-tile (f32x2 packed pixels), double-buffered smem, layer2 via
//     shfl reduction (no smem roundtrip). 3 blocks/SM (~30KB smem, <=84 regs).
// ---------------------------------------------------------------------------
__global__ __launch_bounds__(256, 3) void mod_kernel(
    const float* __restrict__ x, const float* __restrict__ b1,
    const float* __restrict__ w2, const float* __restrict__ b2)
{
    __shared__ float sA[2][KC * BM];     // 2 x 8KB
    __shared__ float sB[2][KC * HID];    // 2 x 4KB
    __shared__ float sImp[8 * BM];       // 4KB
    __shared__ float sW2[NH * HID];
    __shared__ float sB1[HID];
    __shared__ float sB2[NH];

    const int tid = threadIdx.x;
    const int b   = blockIdx.x >> 5;          // 32 tiles of 128px per batch
    const int p0  = (blockIdx.x & 31) << 7;
    const float* xb = x + (size_t)b * CDIM * HW + p0;

    sW2[tid] = w2[tid];
    if (tid < HID) sB1[tid] = b1[tid];
    if (tid < NH)  sB2[tid] = b2[tid];

    // loader mapping
    const int lc  = tid >> 5;                 // 0..7  (c rows, +8 for second)
    const int lp4 = (tid & 31) << 2;          // pixel group of 4
    const int bc  = tid >> 4;                 // 0..15 (w rows)
    const int bo4 = (tid & 15) << 2;          // hid group of 4
    // compute mapping
    const int tx = tid & 15;                  // hid group: o = tx*4..+3
    const int ty = tid >> 4;                  // px group:  p = ty*8..+7

    unsigned long long acc[4][4];
#pragma unroll
    for (int j = 0; j < 4; ++j)
#pragma unroll
        for (int o = 0; o < 4; ++o) acc[j][o] = 0ull;
    float imp4[4] = {0.f, 0.f, 0.f, 0.f};

    float4 ra0, ra1, rb;

    // prologue: chunk 0
    ra0 = *(const float4*)(xb + (size_t)lc * HW + lp4);
    ra1 = *(const float4*)(xb + (size_t)(lc + 8) * HW + lp4);
    rb  = *(const float4*)(g_w1t + bc * HID + bo4);
    *(float4*)(&sA[0][lc * BM + lp4])        = ra0;
    *(float4*)(&sA[0][(lc + 8) * BM + lp4])  = ra1;
    *(float4*)(&sB[0][bc * HID + bo4])       = rb;
    imp4[0] += fabsf(ra0.x) + fabsf(ra1.x);
    imp4[1] += fabsf(ra0.y) + fabsf(ra1.y);
    imp4[2] += fabsf(ra0.z) + fabsf(ra1.z);
    imp4[3] += fabsf(ra0.w) + fabsf(ra1.w);
    __syncthreads();

    int buf = 0;
#pragma unroll 1
    for (int ch = 0; ch < CDIM / KC; ++ch) {
        if (ch < CDIM / KC - 1) {             // prefetch next chunk
            int c0 = (ch + 1) * KC;
            ra0 = *(const float4*)(xb + (size_t)(c0 + lc) * HW + lp4);
            ra1 = *(const float4*)(xb + (size_t)(c0 + lc + 8) * HW + lp4);
            rb  = *(const float4*)(g_w1t + (c0 + bc) * HID + bo4);
        }
        const float* A = &sA[buf][(ty << 3)];
        const float* B = &sB[buf][(tx << 2)];
#pragma unroll
        for (int k = 0; k < KC; ++k) {
            ulonglong2 av0 = *(const ulonglong2*)(A + k * BM);
            ulonglong2 av1 = *(const ulonglong2*)(A + k * BM + 4);
            float4 bv = *(const float4*)(B + k * HID);
            unsigned long long bs0 = splat2(bv.x), bs1 = splat2(bv.y);
            unsigned long long bs2 = splat2(bv.z), bs3 = splat2(bv.w);
            ffma2(acc[0][0], av0.x, bs0); ffma2(acc[0][1], av0.x, bs1);
            ffma2(acc[0][2], av0.x, bs2); ffma2(acc[0][3], av0.x, bs3);
            ffma2(acc[1][0], av0.y, bs0); ffma2(acc[1][1], av0.y, bs1);
            ffma2(acc[1][2], av0.y, bs2); ffma2(acc[1][3], av0.y, bs3);
            ffma2(acc[2][0], av1.x, bs0); ffma2(acc[2][1], av1.x, bs1);
            ffma2(acc[2][2], av1.x, bs2); ffma2(acc[2][3], av1.x, bs3);
            ffma2(acc[3][0], av1.y, bs0); ffma2(acc[3][1], av1.y, bs1);
            ffma2(acc[3][2], av1.y, bs2); ffma2(acc[3][3], av1.y, bs3);
        }
        if (ch < CDIM / KC - 1) {
            __syncthreads();
            buf ^= 1;
            *(float4*)(&sA[buf][lc * BM + lp4])       = ra0;
            *(float4*)(&sA[buf][(lc + 8) * BM + lp4]) = ra1;
            *(float4*)(&sB[buf][bc * HID + bo4])      = rb;
            imp4[0] += fabsf(ra0.x) + fabsf(ra1.x);
            imp4[1] += fabsf(ra0.y) + fabsf(ra1.y);
            imp4[2] += fabsf(ra0.z) + fabsf(ra1.z);
            imp4[3] += fabsf(ra0.w) + fabsf(ra1.w);
            __syncthreads();
        }
    }

    // importance partials (deterministic reduction, no float atomics)
    *(float4*)(&sImp[lc * BM + lp4]) = make_float4(imp4[0], imp4[1], imp4[2], imp4[3]);

    // layer2: z[px][h] partials over this thread's 4-hid slice, then shfl-reduce
    // across tx (16-lane halves; xor masks 1,2,4,8 stay within each half).
    float z[8][NH];
#pragma unroll
    for (int p = 0; p < 8; ++p)
#pragma unroll
        for (int h = 0; h < NH; ++h) z[p][h] = 0.f;

#pragma unroll
    for (int j = 0; j < 4; ++j) {
#pragma unroll
        for (int oo = 0; oo < 4; ++oo) {
            unsigned int lo, hi;
            asm("mov.b64 {%0, %1}, %2;" : "=r"(lo), "=r"(hi) : "l"(acc[j][oo]));
            int o = (tx << 2) + oo;
            float bo = sB1[o];
            float h1lo = fmaxf(__uint_as_float(lo) + bo, 0.f);
            float h1hi = fmaxf(__uint_as_float(hi) + bo, 0.f);
#pragma unroll
            for (int h = 0; h < NH; ++h) {
                float w = sW2[h * HID + o];
                z[2 * j][h]     = fmaf(w, h1lo, z[2 * j][h]);
                z[2 * j + 1][h] = fmaf(w, h1hi, z[2 * j + 1][h]);
            }
        }
    }
#pragma unroll
    for (int s = 1; s < 16; s <<= 1)
#pragma unroll
        for (int p = 0; p < 8; ++p)
#pragma unroll
            for (int h = 0; h < NH; ++h)
                z[p][h] += __shfl_xor_sync(0xffffffffu, z[p][h], s);

    if (tx == 0) {
#pragma unroll
        for (int p = 0; p < 8; ++p) {
            float msum = 0.f;
#pragma unroll
            for (int h = 0; h < NH; ++h)
                msum += 1.f / (1.f + expf(-(z[p][h] + sB2[h])));
            g_scale[b * HW + p0 + (ty << 3) + p] = 0.7f * 0.25f * msum;
        }
    }

    __syncthreads();
    if (tid < BM) {
        float s = 0.f;
#pragma unroll
        for (int l = 0; l < 8; ++l) s += sImp[l * BM + tid];
        g_imp[b * HW + p0 + tid] = s;
    }
}

// ---------------------------------------------------------------------------
// K2: per-batch top-40 tournament; add 0.3/40 to selected pixels.
//     (softmax rows sum to 1 => graph pixel importance == 1/NSEL exactly)
// ---------------------------------------------------------------------------
__global__ __launch_bounds__(1024) void topk_kernel()
{
    __shared__ unsigned long long sW[32];
    __shared__ unsigned long long sBest;
    const int b = blockIdx.x, tid = threadIdx.x;
    const int base = tid << 2;

    float4 v4 = *(const float4*)(g_imp + b * HW + base);
    float v[4] = {v4.x, v4.y, v4.z, v4.w};   // strictly positive sums of |x|

    for (int it = 0; it < NSEL; ++it) {
        unsigned long long k = 0ull;
#pragma unroll
        for (int j = 0; j < 4; ++j) {
            unsigned long long kj =
                ((unsigned long long)__float_as_uint(v[j]) << 32) |
                (unsigned)(HW - 1 - (base + j));   // tie -> lower idx wins
            k = (kj > k) ? kj : k;
        }
#pragma unroll
        for (int s = 16; s; s >>= 1) {
            unsigned long long o = __shfl_xor_sync(0xffffffffu, k, s);
            k = (o > k) ? o : k;
        }
        if ((tid & 31) == 0) sW[tid >> 5] = k;
        __syncthreads();
        if (tid < 32) {
            unsigned long long kk = sW[tid];
#pragma unroll
            for (int s = 16; s; s >>= 1) {
                unsigned long long o = __shfl_xor_sync(0xffffffffu, kk, s);
                kk = (o > kk) ? o : kk;
            }
            if (tid == 0) sBest = kk;
        }
        __syncthreads();
        int idx = (HW - 1) - (int)(unsigned)(sBest & 0xffffffffu);
        if ((idx >> 2) == tid) {
            v[idx & 3] = 0.0f;
            g_scale[b * HW + idx] += 0.3f / (float)NSEL;
        }
    }
}

// ---------------------------------------------------------------------------
// K3: out = x * scale[b,p], float4 vectorized.
// ---------------------------------------------------------------------------
__global__ __launch_bounds__(256) void apply_kernel(const float* __restrict__ x,
                                                    float* __restrict__ out)
{
    int f = blockIdx.x * blockDim.x + threadIdx.x;   // float4 index
    int base = f << 2;
    int b = base >> 20;                              // C*HW = 2^20
    int p = base & (HW - 1);
    float4 xv = __ldg(reinterpret_cast<const float4*>(x) + f);
    float4 sv = *reinterpret_cast<const float4*>(&g_scale[(b << 12) + p]);
    float4 ov;
    ov.x = xv.x * sv.x; ov.y = xv.y * sv.y;
    ov.z = xv.z * sv.z; ov.w = xv.w * sv.w;
    reinterpret_cast<float4*>(out)[f] = ov;
}

// ---------------------------------------------------------------------------
extern "C" void kernel_launch(void* const* d_in, const int* in_sizes, int n_in,
                              void* d_out, int out_size)
{
    const float* x  = (const float*)d_in[0];
    const float* w1 = (const float*)d_in[1];
    const float* b1 = (const float*)d_in[2];
    const float* w2 = (const float*)d_in[3];
    const float* b2 = (const float*)d_in[4];
    float* out = (float*)d_out;

    transpose_w1<<<64, 256>>>(w1);
    mod_kernel<<<BATCH * (HW / BM), 256>>>(x, b1, w2, b2);
    topk_kernel<<<BATCH, 1024>>>();
    apply_kernel<<<(BATCH * CDIM * HW / 4) / 256, 256>>>(x, out);
}

// round 15
// speedup vs baseline: 1.6299x; 1.2115x over previous
#include <cuda_runtime.h>
#include <cuda_bf16.h>
#include <cstdint>

#define HW    4096
#define CDIM  256
#define BATCH 32
#define NH    4
#define HID   64
#define NSEL  40
#define PXB   128     // pixels per block (M)
#define KCH   64      // k per chunk
#define NCH   4       // chunks (K=256)

// Padded smem tiles: rows of 64 bf16 (128B) padded to 144B (16B-aligned, conflict-free)
#define RSTRIDE 144
#define AH_OFF  0
#define AL_OFF  18432
#define BH_OFF  36864
#define BL_OFF  46080
#define SM_DYN  55296
#define H1_STRIDE 272   // epilogue h1 overlay: 68 floats/row (uses dead A region)

// Scratch (device globals: allocation-free rule)
__device__ float g_scale[BATCH * HW];
__device__ float g_imp[BATCH * HW];
__device__ uint4 g_w1h4[NCH * 512];   // W1 hi-split: [ch][o][64] bf16
__device__ uint4 g_w1l4[NCH * 512];   // W1 lo-split

__device__ __forceinline__ uint32_t smem_u32(const void* p) {
    uint32_t a;
    asm("{ .reg .u64 t; cvta.to.shared.u64 t, %1; cvt.u32.u64 %0, t; }"
        : "=r"(a) : "l"(p));
    return a;
}
__device__ __forceinline__ void ldsm4(unsigned* r, uint32_t addr) {
    asm volatile("ldmatrix.sync.aligned.m8n8.x4.shared.b16 {%0,%1,%2,%3}, [%4];"
                 : "=r"(r[0]), "=r"(r[1]), "=r"(r[2]), "=r"(r[3]) : "r"(addr));
}
__device__ __forceinline__ void mma_bf16(float* d, const unsigned* a,
                                         unsigned b0, unsigned b1) {
    asm volatile("mma.sync.aligned.m16n8k16.row.col.f32.bf16.bf16.f32 "
                 "{%0,%1,%2,%3}, {%4,%5,%6,%7}, {%8,%9}, {%0,%1,%2,%3};"
                 : "+f"(d[0]), "+f"(d[1]), "+f"(d[2]), "+f"(d[3])
                 : "r"(a[0]), "r"(a[1]), "r"(a[2]), "r"(a[3]), "r"(b0), "r"(b1));
}

// ---------------------------------------------------------------------------
// K0: split W1 [o][c] into hi/lo bf16, layout [ch][o][64].
// ---------------------------------------------------------------------------
__global__ void split_w1(const float* __restrict__ w1) {
    int i = blockIdx.x * 256 + threadIdx.x;   // 16384 = 64x256
    int o = i >> 8, c = i & 255;
    int ch = c >> 6, cl = c & 63;
    float v = w1[i];
    __nv_bfloat16 hb = __float2bfloat16(v);
    float r = v - __bfloat162float(hb);
    __nv_bfloat16 lb = __float2bfloat16(r);
    int idx = ch * 4096 + o * 64 + cl;
    ((__nv_bfloat16*)g_w1h4)[idx] = hb;
    ((__nv_bfloat16*)g_w1l4)[idx] = lb;
}

// ---------------------------------------------------------------------------
// K1: HMMA modulator. D[128px,64hid] = x@W1^T via 2-way bf16 split (3 terms),
//     mma.sync.m16n8k16, fp32 accum. Fused importance; layer2+sigmoid epilogue.
// ---------------------------------------------------------------------------
extern __shared__ char dynraw[];

__global__ __launch_bounds__(256) void mod_hmma_kernel(
    const float* __restrict__ x,  const float* __restrict__ b1,
    const float* __restrict__ w2, const float* __restrict__ b2)
{
    __shared__ float sW2[NH * HID];
    __shared__ float sB1v[HID];
    __shared__ float sB2v[NH];
    __shared__ float sImp[2 * PXB];

    const int tid  = threadIdx.x;
    const int lane = tid & 31;
    const int wid  = tid >> 5;
    const int wx   = wid & 1;          // hid half (32)
    const int wy   = wid >> 1;         // px quarter (32)

    sW2[tid] = w2[tid];
    if (tid < HID) sB1v[tid] = b1[tid];
    if (tid < NH)  sB2v[tid] = b2[tid];

    const uint32_t base = smem_u32(dynraw);

    // lane-invariant ldmatrix address parts
    const uint32_t aoff = (uint32_t)((lane & 15) * RSTRIDE + (lane >> 4) * 16);
    const uint32_t boff = (uint32_t)((((lane >> 4) * 8) + (lane & 7)) * RSTRIDE +
                                     ((lane >> 3) & 1) * 16);
    const uint32_t aBaseH = base + AH_OFF + (uint32_t)(wy * 32 * RSTRIDE) + aoff;
    const uint32_t aBaseL = base + AL_OFF + (uint32_t)(wy * 32 * RSTRIDE) + aoff;
    const uint32_t bBaseH = base + BH_OFF + (uint32_t)(wx * 32 * RSTRIDE) + boff;
    const uint32_t bBaseL = base + BL_OFF + (uint32_t)(wx * 32 * RSTRIDE) + boff;

    const int b  = blockIdx.x >> 5;            // 32 tiles of 128 px per batch
    const int p0 = (blockIdx.x & 31) << 7;
    const float* xb = x + (size_t)b * CDIM * HW + p0;

    const int px   = tid & 127;
    const int half = tid >> 7;
    float aimp = 0.f;

    float D[2][4][4];
#pragma unroll
    for (int mt = 0; mt < 2; ++mt)
#pragma unroll
        for (int jn = 0; jn < 4; ++jn)
#pragma unroll
            for (int e = 0; e < 4; ++e) D[mt][jn][e] = 0.f;

#pragma unroll 1
    for (int ch = 0; ch < NCH; ++ch) {
        const int c0 = ch * KCH;
        // B tiles: copy pre-split weights into padded rows
        const uint4* gh = g_w1h4 + ch * 512;
        const uint4* gl = g_w1l4 + ch * 512;
        for (int i = tid; i < 512; i += 256) {
            int row = i >> 3, seg = i & 7;
            *(uint4*)(dynraw + BH_OFF + row * RSTRIDE + seg * 16) = gh[i];
            *(uint4*)(dynraw + BL_OFF + row * RSTRIDE + seg * 16) = gl[i];
        }
        // A tiles: load fp32, split hi/lo, STS.128 into padded rows
#pragma unroll
        for (int i = 0; i < 4; ++i) {
            const int cl = (i * 2 + half) * 8;
            float v[8];
#pragma unroll
            for (int j = 0; j < 8; ++j)
                v[j] = __ldg(xb + (size_t)(c0 + cl + j) * HW + px);
#pragma unroll
            for (int j = 0; j < 8; ++j) aimp += fabsf(v[j]);
            uint32_t hh[4], ll[4];
#pragma unroll
            for (int j2 = 0; j2 < 4; ++j2) {
                float v0 = v[2 * j2], v1 = v[2 * j2 + 1];
                __nv_bfloat16 h0 = __float2bfloat16(v0);
                __nv_bfloat16 h1 = __float2bfloat16(v1);
                float r0 = v0 - __bfloat162float(h0);
                float r1 = v1 - __bfloat162float(h1);
                __nv_bfloat162 hp(h0, h1), lp(__float2bfloat16(r0), __float2bfloat16(r1));
                hh[j2] = *(uint32_t*)&hp;
                ll[j2] = *(uint32_t*)&lp;
            }
            *(uint4*)(dynraw + AH_OFF + px * RSTRIDE + cl * 2) =
                make_uint4(hh[0], hh[1], hh[2], hh[3]);
            *(uint4*)(dynraw + AL_OFF + px * RSTRIDE + cl * 2) =
                make_uint4(ll[0], ll[1], ll[2], ll[3]);
        }
        __syncthreads();

#pragma unroll
        for (int ks = 0; ks < 4; ++ks) {
            const uint32_t ko = (uint32_t)(ks * 32);
            unsigned Ah[2][4], Al[2][4], Bh[2][4], Bl[2][4];
            ldsm4(Ah[0], aBaseH + ko);
            ldsm4(Ah[1], aBaseH + 16 * RSTRIDE + ko);
            ldsm4(Al[0], aBaseL + ko);
            ldsm4(Al[1], aBaseL + 16 * RSTRIDE + ko);
            ldsm4(Bh[0], bBaseH + ko);
            ldsm4(Bh[1], bBaseH + 16 * RSTRIDE + ko);
            ldsm4(Bl[0], bBaseL + ko);
            ldsm4(Bl[1], bBaseL + 16 * RSTRIDE + ko);
#pragma unroll
            for (int mt = 0; mt < 2; ++mt)
#pragma unroll
                for (int jp = 0; jp < 2; ++jp)
#pragma unroll
                    for (int jt = 0; jt < 2; ++jt) {
                        float* d = D[mt][jp * 2 + jt];
                        mma_bf16(d, Ah[mt], Bh[jp][jt * 2], Bh[jp][jt * 2 + 1]);
                        mma_bf16(d, Ah[mt], Bl[jp][jt * 2], Bl[jp][jt * 2 + 1]);
                        mma_bf16(d, Al[mt], Bh[jp][jt * 2], Bh[jp][jt * 2 + 1]);
                    }
        }
        __syncthreads();   // before next chunk overwrites tiles
    }

    sImp[half * PXB + px] = aimp;

    // h1 = relu(D + b1) -> smem overlay on dead A region, [px][68f] rows
    {
        const int prow  = wy * 32 + (lane >> 2);
        const int cbase = wx * 32 + 2 * (lane & 3);
#pragma unroll
        for (int mt = 0; mt < 2; ++mt)
#pragma unroll
            for (int jn = 0; jn < 4; ++jn) {
                const int c = cbase + jn * 8;
                const int r = prow + mt * 16;
                float bc0 = sB1v[c], bc1 = sB1v[c + 1];
                float2 v01, v23;
                v01.x = fmaxf(D[mt][jn][0] + bc0, 0.f);
                v01.y = fmaxf(D[mt][jn][1] + bc1, 0.f);
                v23.x = fmaxf(D[mt][jn][2] + bc0, 0.f);
                v23.y = fmaxf(D[mt][jn][3] + bc1, 0.f);
                *(float2*)(dynraw + r * H1_STRIDE + c * 4)       = v01;
                *(float2*)(dynraw + (r + 8) * H1_STRIDE + c * 4) = v23;
            }
    }
    __syncthreads();

    if (tid < PXB) {
        const float* h1 = (const float*)(dynraw + tid * H1_STRIDE);
        float z[NH];
#pragma unroll
        for (int h = 0; h < NH; ++h) z[h] = sB2v[h];
#pragma unroll
        for (int j = 0; j < HID; ++j) {
            float hv = h1[j];
#pragma unroll
            for (int h = 0; h < NH; ++h) z[h] = fmaf(sW2[h * HID + j], hv, z[h]);
        }
        float msum = 0.f;
#pragma unroll
        for (int h = 0; h < NH; ++h) msum += 1.f / (1.f + expf(-z[h]));
        g_scale[b * HW + p0 + tid] = 0.7f * 0.25f * msum;
        g_imp[b * HW + p0 + tid]   = sImp[tid] + sImp[PXB + tid];
    }
}

// ---------------------------------------------------------------------------
// K2: per-batch top-40 tournament; add 0.3/40 to selected pixels.
//     (softmax rows sum to 1 => graph pixel importance == 1/NSEL exactly)
// ---------------------------------------------------------------------------
__global__ __launch_bounds__(1024) void topk_kernel()
{
    __shared__ unsigned long long sW[32];
    __shared__ unsigned long long sBest;
    const int b = blockIdx.x, tid = threadIdx.x;
    const int base = tid << 2;

    float4 v4 = *(const float4*)(g_imp + b * HW + base);
    float v[4] = {v4.x, v4.y, v4.z, v4.w};   // strictly positive sums of |x|

    for (int it = 0; it < NSEL; ++it) {
        unsigned long long k = 0ull;
#pragma unroll
        for (int j = 0; j < 4; ++j) {
            unsigned long long kj =
                ((unsigned long long)__float_as_uint(v[j]) << 32) |
                (unsigned)(HW - 1 - (base + j));   // tie -> lower idx wins
            k = (kj > k) ? kj : k;
        }
#pragma unroll
        for (int s = 16; s; s >>= 1) {
            unsigned long long o = __shfl_xor_sync(0xffffffffu, k, s);
            k = (o > k) ? o : k;
        }
        if ((tid & 31) == 0) sW[tid >> 5] = k;
        __syncthreads();
        if (tid < 32) {
            unsigned long long kk = sW[tid];
#pragma unroll
            for (int s = 16; s; s >>= 1) {
                unsigned long long o = __shfl_xor_sync(0xffffffffu, kk, s);
                kk = (o > kk) ? o : kk;
            }
            if (tid == 0) sBest = kk;
        }
        __syncthreads();
        int idx = (HW - 1) - (int)(unsigned)(sBest & 0xffffffffu);
        if ((idx >> 2) == tid) {
            v[idx & 3] = 0.0f;
            g_scale[b * HW + idx] += 0.3f / (float)NSEL;
        }
    }
}

// ---------------------------------------------------------------------------
// K3: out = x * scale[b,p], float4 vectorized.
// ---------------------------------------------------------------------------
__global__ __launch_bounds__(256) void apply_kernel(const float* __restrict__ x,
                                                    float* __restrict__ out)
{
    int f = blockIdx.x * blockDim.x + threadIdx.x;   // float4 index
    int base = f << 2;
    int b = base >> 20;                              // C*HW = 2^20
    int p = base & (HW - 1);
    float4 xv = __ldg(reinterpret_cast<const float4*>(x) + f);
    float4 sv = *reinterpret_cast<const float4*>(&g_scale[(b << 12) + p]);
    float4 ov;
    ov.x = xv.x * sv.x; ov.y = xv.y * sv.y;
    ov.z = xv.z * sv.z; ov.w = xv.w * sv.w;
    reinterpret_cast<float4*>(out)[f] = ov;
}

// ---------------------------------------------------------------------------
extern "C" void kernel_launch(void* const* d_in, const int* in_sizes, int n_in,
                              void* d_out, int out_size)
{
    const float* x  = (const float*)d_in[0];
    const float* w1 = (const float*)d_in[1];
    const float* b1 = (const float*)d_in[2];
    const float* w2 = (const float*)d_in[3];
    const float* b2 = (const float*)d_in[4];
    float* out = (float*)d_out;

    (void)cudaFuncSetAttribute(mod_hmma_kernel,
                               cudaFuncAttributeMaxDynamicSharedMemorySize, SM_DYN);

    split_w1<<<64, 256>>>(w1);
    mod_hmma_kernel<<<BATCH * (HW / PXB), 256, SM_DYN>>>(x, b1, w2, b2);
    topk_kernel<<<BATCH, 1024>>>();
    apply_kernel<<<(BATCH * CDIM * HW / 4) / 256, 256>>>(x, out);
}

// round 17
// speedup vs baseline: 1.8060x; 1.1080x over previous
#include <cuda_runtime.h>
#include <cuda_bf16.h>
#include <cstdint>

#define HW    4096
#define CDIM  256
#define BATCH 32
#define NH    4
#define HID   64
#define NSEL  40
#define PXB   128     // pixels per block (M)
#define KCH   64      // k per chunk
#define NCH   4       // chunks (K=256)

// Padded smem tiles: rows of 64 bf16 (128B) padded to 144B (16B-aligned, conflict-free)
#define RSTRIDE 144
#define AH_OFF  0
#define AL_OFF  18432
#define BH_OFF  36864
#define BL_OFF  46080
#define SM_DYN  55296
#define H1_STRIDE 272   // epilogue h1 overlay: 68 floats/row (uses dead A region)

// Scratch (device globals: allocation-free rule)
__device__ float g_scale[BATCH * HW];
__device__ float g_imp[BATCH * HW];
__device__ uint4 g_w1h4[NCH * 512];   // W1 hi-split: [ch][o][64] bf16
__device__ uint4 g_w1l4[NCH * 512];   // W1 lo-split

__device__ __forceinline__ uint32_t smem_u32(const void* p) {
    uint32_t a;
    asm("{ .reg .u64 t; cvta.to.shared.u64 t, %1; cvt.u32.u64 %0, t; }"
        : "=r"(a) : "l"(p));
    return a;
}
__device__ __forceinline__ void ldsm4(unsigned* r, uint32_t addr) {
    asm volatile("ldmatrix.sync.aligned.m8n8.x4.shared.b16 {%0,%1,%2,%3}, [%4];"
                 : "=r"(r[0]), "=r"(r[1]), "=r"(r[2]), "=r"(r[3]) : "r"(addr));
}
__device__ __forceinline__ void mma_bf16(float* d, const unsigned* a,
                                         unsigned b0, unsigned b1) {
    asm volatile("mma.sync.aligned.m16n8k16.row.col.f32.bf16.bf16.f32 "
                 "{%0,%1,%2,%3}, {%4,%5,%6,%7}, {%8,%9}, {%0,%1,%2,%3};"
                 : "+f"(d[0]), "+f"(d[1]), "+f"(d[2]), "+f"(d[3])
                 : "r"(a[0]), "r"(a[1]), "r"(a[2]), "r"(a[3]), "r"(b0), "r"(b1));
}

// ---------------------------------------------------------------------------
// K0: split W1 [o][c] into hi/lo bf16, layout [ch][o][64].
// ---------------------------------------------------------------------------
__global__ void split_w1(const float* __restrict__ w1) {
    int i = blockIdx.x * 256 + threadIdx.x;   // 16384 = 64x256
    int o = i >> 8, c = i & 255;
    int ch = c >> 6, cl = c & 63;
    float v = w1[i];
    __nv_bfloat16 hb = __float2bfloat16(v);
    float r = v - __bfloat162float(hb);
    __nv_bfloat16 lb = __float2bfloat16(r);
    int idx = ch * 4096 + o * 64 + cl;
    ((__nv_bfloat16*)g_w1h4)[idx] = hb;
    ((__nv_bfloat16*)g_w1l4)[idx] = lb;
}

// ---------------------------------------------------------------------------
// K1: HMMA modulator with register-prefetch pipeline.
//     D[128px,64hid] = x@W1^T via 2-way bf16 split (3 terms), fp32 accum.
//     Next chunk's x-LDGs issued BEFORE current chunk's MMA loop.
// ---------------------------------------------------------------------------
extern __shared__ char dynraw[];

__global__ __launch_bounds__(256) void mod_hmma_kernel(
    const float* __restrict__ x,  const float* __restrict__ b1,
    const float* __restrict__ w2, const float* __restrict__ b2)
{
    __shared__ float sW2[NH * HID];
    __shared__ float sB1v[HID];
    __shared__ float sB2v[NH];
    __shared__ float sImp[2 * PXB];

    const int tid  = threadIdx.x;
    const int lane = tid & 31;
    const int wid  = tid >> 5;
    const int wx   = wid & 1;          // hid half (32)
    const int wy   = wid >> 1;         // px quarter (32)

    sW2[tid] = w2[tid];
    if (tid < HID) sB1v[tid] = b1[tid];
    if (tid < NH)  sB2v[tid] = b2[tid];

    const uint32_t base = smem_u32(dynraw);

    // lane-invariant ldmatrix address parts
    const uint32_t aoff = (uint32_t)((lane & 15) * RSTRIDE + (lane >> 4) * 16);
    const uint32_t boff = (uint32_t)((((lane >> 4) * 8) + (lane & 7)) * RSTRIDE +
                                     ((lane >> 3) & 1) * 16);
    const uint32_t aBaseH = base + AH_OFF + (uint32_t)(wy * 32 * RSTRIDE) + aoff;
    const uint32_t aBaseL = base + AL_OFF + (uint32_t)(wy * 32 * RSTRIDE) + aoff;
    const uint32_t bBaseH = base + BH_OFF + (uint32_t)(wx * 32 * RSTRIDE) + boff;
    const uint32_t bBaseL = base + BL_OFF + (uint32_t)(wx * 32 * RSTRIDE) + boff;

    const int b  = blockIdx.x >> 5;            // 32 tiles of 128 px per batch
    const int p0 = (blockIdx.x & 31) << 7;
    const float* xb = x + (size_t)b * CDIM * HW + p0;

    const int px   = tid & 127;
    const int half = tid >> 7;
    float aimp = 0.f;

    float D[2][4][4];
#pragma unroll
    for (int mt = 0; mt < 2; ++mt)
#pragma unroll
        for (int jn = 0; jn < 4; ++jn)
#pragma unroll
            for (int e = 0; e < 4; ++e) D[mt][jn][e] = 0.f;

    float pv[4][8];   // prefetched x for the next chunk

    // convert+store helper phase (uses pv of chunk `cc`), accumulates aimp
    auto stage_a = [&](void) {
#pragma unroll
        for (int i = 0; i < 4; ++i) {
            const int cl = (i * 2 + half) * 8;
            uint32_t hh[4], ll[4];
#pragma unroll
            for (int j = 0; j < 8; ++j) aimp += fabsf(pv[i][j]);
#pragma unroll
            for (int j2 = 0; j2 < 4; ++j2) {
                float v0 = pv[i][2 * j2], v1 = pv[i][2 * j2 + 1];
                __nv_bfloat16 h0 = __float2bfloat16(v0);
                __nv_bfloat16 h1 = __float2bfloat16(v1);
                float r0 = v0 - __bfloat162float(h0);
                float r1 = v1 - __bfloat162float(h1);
                __nv_bfloat162 hp(h0, h1), lp(__float2bfloat16(r0), __float2bfloat16(r1));
                hh[j2] = *(uint32_t*)&hp;
                ll[j2] = *(uint32_t*)&lp;
            }
            *(uint4*)(dynraw + AH_OFF + px * RSTRIDE + cl * 2) =
                make_uint4(hh[0], hh[1], hh[2], hh[3]);
            *(uint4*)(dynraw + AL_OFF + px * RSTRIDE + cl * 2) =
                make_uint4(ll[0], ll[1], ll[2], ll[3]);
        }
    };
    auto load_a = [&](int ch) {
        const int c0 = ch * KCH;
#pragma unroll
        for (int i = 0; i < 4; ++i) {
            const int cl = (i * 2 + half) * 8;
#pragma unroll
            for (int j = 0; j < 8; ++j)
                pv[i][j] = __ldg(xb + (size_t)(c0 + cl + j) * HW + px);
        }
    };
    auto stage_b = [&](int ch) {
        const uint4* gh = g_w1h4 + ch * 512;
        const uint4* gl = g_w1l4 + ch * 512;
        for (int i = tid; i < 512; i += 256) {
            int row = i >> 3, seg = i & 7;
            *(uint4*)(dynraw + BH_OFF + row * RSTRIDE + seg * 16) = gh[i];
            *(uint4*)(dynraw + BL_OFF + row * RSTRIDE + seg * 16) = gl[i];
        }
    };

    // prologue: chunk 0 staged
    load_a(0);
    stage_a();
    stage_b(0);
    __syncthreads();

#pragma unroll 1
    for (int ch = 0; ch < NCH; ++ch) {
        if (ch + 1 < NCH) load_a(ch + 1);   // LDGs in flight during MMA below

#pragma unroll
        for (int ks = 0; ks < 4; ++ks) {
            const uint32_t ko = (uint32_t)(ks * 32);
            unsigned Ah[2][4], Al[2][4], Bh[2][4], Bl[2][4];
            ldsm4(Ah[0], aBaseH + ko);
            ldsm4(Ah[1], aBaseH + 16 * RSTRIDE + ko);
            ldsm4(Al[0], aBaseL + ko);
            ldsm4(Al[1], aBaseL + 16 * RSTRIDE + ko);
            ldsm4(Bh[0], bBaseH + ko);
            ldsm4(Bh[1], bBaseH + 16 * RSTRIDE + ko);
            ldsm4(Bl[0], bBaseL + ko);
            ldsm4(Bl[1], bBaseL + 16 * RSTRIDE + ko);
#pragma unroll
            for (int mt = 0; mt < 2; ++mt)
#pragma unroll
                for (int jp = 0; jp < 2; ++jp)
#pragma unroll
                    for (int jt = 0; jt < 2; ++jt) {
                        float* d = D[mt][jp * 2 + jt];
                        mma_bf16(d, Ah[mt], Bh[jp][jt * 2], Bh[jp][jt * 2 + 1]);
                        mma_bf16(d, Ah[mt], Bl[jp][jt * 2], Bl[jp][jt * 2 + 1]);
                        mma_bf16(d, Al[mt], Bh[jp][jt * 2], Bh[jp][jt * 2 + 1]);
                    }
        }
        __syncthreads();                    // tiles consumed
        if (ch + 1 < NCH) {
            stage_a();                      // prefetched data has arrived
            stage_b(ch + 1);
            __syncthreads();
        }
    }

    sImp[half * PXB + px] = aimp;

    // h1 = relu(D + b1) -> smem overlay on dead A region, [px][68f] rows
    {
        const int prow  = wy * 32 + (lane >> 2);
        const int cbase = wx * 32 + 2 * (lane & 3);
#pragma unroll
        for (int mt = 0; mt < 2; ++mt)
#pragma unroll
            for (int jn = 0; jn < 4; ++jn) {
                const int c = cbase + jn * 8;
                const int r = prow + mt * 16;
                float bc0 = sB1v[c], bc1 = sB1v[c + 1];
                float2 v01, v23;
                v01.x = fmaxf(D[mt][jn][0] + bc0, 0.f);
                v01.y = fmaxf(D[mt][jn][1] + bc1, 0.f);
                v23.x = fmaxf(D[mt][jn][2] + bc0, 0.f);
                v23.y = fmaxf(D[mt][jn][3] + bc1, 0.f);
                *(float2*)(dynraw + r * H1_STRIDE + c * 4)       = v01;
                *(float2*)(dynraw + (r + 8) * H1_STRIDE + c * 4) = v23;
            }
    }
    __syncthreads();

    if (tid < PXB) {
        const float* h1 = (const float*)(dynraw + tid * H1_STRIDE);
        float z[NH];
#pragma unroll
        for (int h = 0; h < NH; ++h) z[h] = sB2v[h];
#pragma unroll
        for (int j = 0; j < HID; ++j) {
            float hv = h1[j];
#pragma unroll
            for (int h = 0; h < NH; ++h) z[h] = fmaf(sW2[h * HID + j], hv, z[h]);
        }
        float msum = 0.f;
#pragma unroll
        for (int h = 0; h < NH; ++h) msum += 1.f / (1.f + expf(-z[h]));
        g_scale[b * HW + p0 + tid] = 0.7f * 0.25f * msum;
        g_imp[b * HW + p0 + tid]   = sImp[tid] + sImp[PXB + tid];
    }
}

// ---------------------------------------------------------------------------
// K2: per-batch top-40 tournament; add 0.3/40 to selected pixels.
//     (softmax rows sum to 1 => graph pixel importance == 1/NSEL exactly)
// ---------------------------------------------------------------------------
__global__ __launch_bounds__(1024) void topk_kernel()
{
    __shared__ unsigned long long sW[32];
    __shared__ unsigned long long sBest;
    const int b = blockIdx.x, tid = threadIdx.x;
    const int base = tid << 2;

    float4 v4 = *(const float4*)(g_imp + b * HW + base);
    float v[4] = {v4.x, v4.y, v4.z, v4.w};   // strictly positive sums of |x|

    for (int it = 0; it < NSEL; ++it) {
        unsigned long long k = 0ull;
#pragma unroll
        for (int j = 0; j < 4; ++j) {
            unsigned long long kj =
                ((unsigned long long)__float_as_uint(v[j]) << 32) |
                (unsigned)(HW - 1 - (base + j));   // tie -> lower idx wins
            k = (kj > k) ? kj : k;
        }
#pragma unroll
        for (int s = 16; s; s >>= 1) {
            unsigned long long o = __shfl_xor_sync(0xffffffffu, k, s);
            k = (o > k) ? o : k;
        }
        if ((tid & 31) == 0) sW[tid >> 5] = k;
        __syncthreads();
        if (tid < 32) {
            unsigned long long kk = sW[tid];
#pragma unroll
            for (int s = 16; s; s >>= 1) {
                unsigned long long o = __shfl_xor_sync(0xffffffffu, kk, s);
                kk = (o > kk) ? o : kk;
            }
            if (tid == 0) sBest = kk;
        }
        __syncthreads();
        int idx = (HW - 1) - (int)(unsigned)(sBest & 0xffffffffu);
        if ((idx >> 2) == tid) {
            v[idx & 3] = 0.0f;
            g_scale[b * HW + idx] += 0.3f / (float)NSEL;
        }
    }
}

// ---------------------------------------------------------------------------
// K3: out = x * scale[b,p], 2 independent float4s per thread (higher MLP).
// ---------------------------------------------------------------------------
__global__ __launch_bounds__(256) void apply_kernel(const float* __restrict__ x,
                                                    float* __restrict__ out)
{
    int f0 = blockIdx.x * 512 + threadIdx.x;         // float4 indices f0, f0+256
    int f1 = f0 + 256;
    int e0 = f0 << 2, e1 = f1 << 2;
    float4 xv0 = __ldg(reinterpret_cast<const float4*>(x) + f0);
    float4 xv1 = __ldg(reinterpret_cast<const float4*>(x) + f1);
    float4 sv0 = *reinterpret_cast<const float4*>(
        &g_scale[((e0 >> 20) << 12) + (e0 & (HW - 1))]);
    float4 sv1 = *reinterpret_cast<const float4*>(
        &g_scale[((e1 >> 20) << 12) + (e1 & (HW - 1))]);
    float4 o0, o1;
    o0.x = xv0.x * sv0.x; o0.y = xv0.y * sv0.y;
    o0.z = xv0.z * sv0.z; o0.w = xv0.w * sv0.w;
    o1.x = xv1.x * sv1.x; o1.y = xv1.y * sv1.y;
    o1.z = xv1.z * sv1.z; o1.w = xv1.w * sv1.w;
    reinterpret_cast<float4*>(out)[f0] = o0;
    reinterpret_cast<float4*>(out)[f1] = o1;
}

// ---------------------------------------------------------------------------
extern "C" void kernel_launch(void* const* d_in, const int* in_sizes, int n_in,
                              void* d_out, int out_size)
{
    const float* x  = (const float*)d_in[0];
    const float* w1 = (const float*)d_in[1];
    const float* b1 = (const float*)d_in[2];
    const float* w2 = (const float*)d_in[3];
    const float* b2 = (const float*)d_in[4];
    float* out = (float*)d_out;

    (void)cudaFuncSetAttribute(mod_hmma_kernel,
                               cudaFuncAttributeMaxDynamicSharedMemorySize, SM_DYN);

    split_w1<<<64, 256>>>(w1);
    mod_hmma_kernel<<<BATCH * (HW / PXB), 256, SM_DYN>>>(x, b1, w2, b2);
    topk_kernel<<<BATCH, 1024>>>();
    apply_kernel<<<(BATCH * CDIM * HW / 4) / 512, 256>>>(x, out);
}